// round 17
// baseline (speedup 1.0000x reference)
#include <cuda_runtime.h>
#include <cuda_fp16.h>
#include <math.h>
#include <stdint.h>

#define BB 8
#define LL 2048
#define WW 1024
#define KK 5
#define GG 2
#define CI 512
#define CO 512
#define RDIM (KK*CI)        // 2560

// GEMM tiling
#define MT   64             // M per CTA
#define NTT  128            // N per CTA
#define KCB  32             // K-chunk (fp16 elems)
#define NCH  (RDIM/KCB)     // 80 chunks
#define NQ   16             // n32 quads per group (512/32)
#define QS   (NCH*4*32)     // uint4 stride between n-quads

// ---- static scratch ----
// B fragments: [g][nbq][ch][b4][lane] uint4 = {b0_ks0, b1_ks0, b0_ks1, b1_ks1}
__device__ uint4 g_Bf4[GG*NQ*NCH*4*32];       // 5.2 MB
__device__ __half g_xh[(size_t)BB*LL*WW];     // fp16 copy of x, 32 MB
__device__ int   g_p0[BB*LL*KK];
__device__ float g_frac[BB*LL*KK];
__device__ float g_h[(size_t)BB*LL*WW];       // conv output, 64 MB
__device__ float g_s[BB*LL];

// ============================================================
__device__ __forceinline__ uint32_t smem_u32(const void* p) {
    uint32_t a;
    asm("{ .reg .u64 t; cvta.to.shared.u64 t, %1; cvt.u32.u64 %0, t; }" : "=r"(a) : "l"(p));
    return a;
}
#define LDSM4(r, addr) \
    asm volatile("ldmatrix.sync.aligned.m8n8.x4.shared.b16 {%0,%1,%2,%3}, [%4];" \
        : "=r"((r)[0]), "=r"((r)[1]), "=r"((r)[2]), "=r"((r)[3]) : "r"(addr))
#define MMA16816(d, a, b0, b1) \
    asm volatile("mma.sync.aligned.m16n8k16.row.col.f32.f16.f16.f32 " \
        "{%0,%1,%2,%3}, {%4,%5,%6,%7}, {%8,%9}, {%0,%1,%2,%3};" \
        : "+f"((d)[0]), "+f"((d)[1]), "+f"((d)[2]), "+f"((d)[3]) \
        : "r"((a)[0]), "r"((a)[1]), "r"((a)[2]), "r"((a)[3]), "r"(b0), "r"(b1))

// ============================================================
// Kernel 1: B prep — conv_w [g][o][c][k] -> packed fragment order
// ============================================================
__global__ void prep_b_kernel(const float* __restrict__ conv_w) {
    int idx = blockIdx.x * 256 + threadIdx.x;
    if (idx >= GG*NQ*NCH*4*32) return;
    int lane = idx & 31;
    int nbl  = (idx >> 5) & 3;
    int ch   = (idx >> 7) % NCH;
    int nbq  = ((idx >> 7) / NCH) % NQ;
    int g    = idx / (32*4*NCH*NQ);
    int n = (nbq*4 + nbl)*8 + (lane >> 2);   // out channel within group
    const float* wb = conv_w + ((size_t)(g*CO + n))*CI*KK;
    uint32_t packed[4];
    #pragma unroll
    for (int ks = 0; ks < 2; ks++) {
        int r = (ch*2 + ks)*16 + (lane & 3)*2;   // reduction index = ktap*CI + c
        float v0 = wb[(r       % CI)*KK + (r       / CI)];
        float v1 = wb[((r+1)   % CI)*KK + ((r+1)   / CI)];
        float v2 = wb[((r+8)   % CI)*KK + ((r+8)   / CI)];
        float v3 = wb[((r+9)   % CI)*KK + ((r+9)   / CI)];
        __half2 b0 = __floats2half2_rn(v0, v1);
        __half2 b1 = __floats2half2_rn(v2, v3);
        packed[ks*2+0] = *(uint32_t*)&b0;
        packed[ks*2+1] = *(uint32_t*)&b1;
    }
    g_Bf4[idx] = make_uint4(packed[0], packed[1], packed[2], packed[3]);
}

// ============================================================
// Kernel 2: offsets + x->fp16 conversion (fused)
// ============================================================
__global__ void offsets_kernel(const float* __restrict__ x,
                               const float* __restrict__ w_off,
                               const float* __restrict__ b_off) {
    int row = blockIdx.x;
    int tid = threadIdx.x;                // 128
    const float* xr = x + (size_t)row * WW;
    __half* xhr = g_xh + (size_t)row * WW;
    float acc[KK] = {0.f, 0.f, 0.f, 0.f, 0.f};
    for (int w = tid; w < WW; w += 128) {
        float xv = xr[w];
        xhr[w] = __float2half_rn(xv);
        #pragma unroll
        for (int k = 0; k < KK; k++) acc[k] += xv * w_off[w*KK + k];
    }
    __shared__ float sh[KK][128];
    #pragma unroll
    for (int k = 0; k < KK; k++) sh[k][tid] = acc[k];
    __syncthreads();
    for (int s = 64; s > 0; s >>= 1) {
        if (tid < s) {
            #pragma unroll
            for (int k = 0; k < KK; k++) sh[k][tid] += sh[k][tid + s];
        }
        __syncthreads();
    }
    if (tid < KK) {
        int k = tid;
        float off = tanhf(sh[k][0] + b_off[k]) * 2.0f;
        int l = row & (LL - 1);
        float pos = (float)l + ((float)k - 2.0f) + off;
        float p0 = floorf(pos);
        g_p0[row*KK + k]   = (int)p0;
        g_frac[row*KK + k] = pos - p0;
    }
}

// ============================================================
// Kernel 3: fp16 HMMA gathered GEMM; A via SMEM, B via packed fragment LDG
// grid (GG*4, 256); 128 threads = 4 warps (2m x 2n), warp tile 32x64
// SMEM stage (4KB): A only; 2 stages = 8KB
// ============================================================
#define SA(s)   ((s)*4096)
#define SMEM_CONV (2*4096)

__global__ void __launch_bounds__(128, 3) conv_mma_kernel() {
    extern __shared__ __align__(128) char smem[];
    const uint32_t sb = smem_u32(smem);

    const int tid  = threadIdx.x;
    const int lane = tid & 31;
    const int wid  = tid >> 5;           // 0..3

    const int g      = blockIdx.x >> 2;
    const int n_base = (blockIdx.x & 3) * NTT;
    const int m_base = blockIdx.y * MT;

    // ---- A loader mapping: thread t -> (row = t>>1 in 0..63, groups 2*(t&1), +1) ----
    const int lrow  = tid >> 1;
    const int lgrp2 = (tid & 1) * 2;
    const int mg    = m_base + lrow;
    const __half* xb = g_xh + ((size_t)(mg >> 11)) * LL * WW + g * CI + lgrp2 * 8;
    const int*   p0p = &g_p0[mg * KK];
    const float* frp = &g_frac[mg * KK];
    const uint32_t swzrow = (uint32_t)((lrow >> 1) & 3);
    const uint32_t offSTA0 = (uint32_t)(lrow * 64 + (((uint32_t)lgrp2       ^ swzrow) << 4));
    const uint32_t offSTA1 = (uint32_t)(lrow * 64 + (((uint32_t)(lgrp2 + 1) ^ swzrow) << 4));

    // ---- compute mapping: 4 warps = 2m x 2n, warp tile 32x64 ----
    const int wm = (wid & 1) * 32;
    const int wn = (wid >> 1) * 64;
    const int rA0 = wm + (lane & 15), rA1 = rA0 + 16;
    const int sA0 = (rA0 >> 1) & 3, sA1 = (rA1 >> 1) & 3;
    const int hi16 = lane >> 4;
    uint32_t oA0k[2], oA1k[2];
    #pragma unroll
    for (int ks = 0; ks < 2; ks++) {
        int grp = ks * 2 + hi16;
        oA0k[ks] = (uint32_t)(rA0 * 64 + ((grp ^ sA0) << 4));
        oA1k[ks] = (uint32_t)(rA1 * 64 + ((grp ^ sA1) << 4));
    }

    // B fragment pointers: two n-quads per warp
    const uint4* bp  = g_Bf4 + ((size_t)(g*NQ + ((n_base + wn) >> 5)) * NCH) * 4 * 32 + lane;
    const uint4* bp2 = bp + QS;

    float acc[2][8][4];
    #pragma unroll
    for (int mi = 0; mi < 2; mi++)
        #pragma unroll
        for (int nt = 0; nt < 8; nt++)
            #pragma unroll
            for (int e = 0; e < 4; e++) acc[mi][nt][e] = 0.f;

    // staging registers
    uint4 xv00, xv01, xv10, xv11;
    float lfrac;
    uint4 bfr[8];

    auto LOADA = [&](int ch) {
        int ktap = ch >> 4;
        int c0   = (ch & 15) * KCB;
        int p0   = p0p[ktap];
        lfrac    = frp[ktap];
        int ok0 = (p0 >= 0) & (p0 < LL);
        int ok1 = (p0 >= -1) & (p0 < LL - 1);
        const __half* pa = xb + c0 + (size_t)p0 * WW;
        uint4 z = make_uint4(0u, 0u, 0u, 0u);
        xv00 = z; xv01 = z; xv10 = z; xv11 = z;
        if (ok0) { xv00 = *(const uint4*)(pa);      xv01 = *(const uint4*)(pa + 8); }
        if (ok1) { xv10 = *(const uint4*)(pa + WW); xv11 = *(const uint4*)(pa + WW + 8); }
    };

    auto LOADB = [&]() {
        bfr[0] = bp[0];  bfr[1] = bp[32];  bfr[2] = bp[64];  bfr[3] = bp[96];
        bfr[4] = bp2[0]; bfr[5] = bp2[32]; bfr[6] = bp2[64]; bfr[7] = bp2[96];
        bp += 128; bp2 += 128;
    };

    auto STORESA = [&](int s) {
        float w0 = 1.0f - lfrac, w1 = lfrac;
        const __half2* ha0 = (const __half2*)&xv00;
        const __half2* ha1 = (const __half2*)&xv10;
        const __half2* hb0 = (const __half2*)&xv01;
        const __half2* hb1 = (const __half2*)&xv11;
        __half2 hva[4], hvb[4];
        #pragma unroll
        for (int e = 0; e < 4; e++) {
            float2 f0 = __half22float2(ha0[e]);
            float2 f1 = __half22float2(ha1[e]);
            hva[e] = __floats2half2_rn(f0.x * w0 + f1.x * w1,
                                       f0.y * w0 + f1.y * w1);
            float2 g0 = __half22float2(hb0[e]);
            float2 g1 = __half22float2(hb1[e]);
            hvb[e] = __floats2half2_rn(g0.x * w0 + g1.x * w1,
                                       g0.y * w0 + g1.y * w1);
        }
        *(uint4*)(smem + SA(s) + offSTA0) = *(uint4*)hva;
        *(uint4*)(smem + SA(s) + offSTA1) = *(uint4*)hvb;
    };

    auto COMPUTE = [&](int s) {
        const uint32_t bAs = sb + SA(s);
        // ks = 0
        {
            uint32_t ah0[4], ah1[4];
            LDSM4(ah0, bAs + oA0k[0]);
            LDSM4(ah1, bAs + oA1k[0]);
            #pragma unroll
            for (int nb = 0; nb < 8; nb++) {
                MMA16816(acc[0][nb], ah0, bfr[nb].x, bfr[nb].y);
                MMA16816(acc[1][nb], ah1, bfr[nb].x, bfr[nb].y);
            }
        }
        // ks = 1
        {
            uint32_t ah0[4], ah1[4];
            LDSM4(ah0, bAs + oA0k[1]);
            LDSM4(ah1, bAs + oA1k[1]);
            #pragma unroll
            for (int nb = 0; nb < 8; nb++) {
                MMA16816(acc[0][nb], ah0, bfr[nb].z, bfr[nb].w);
                MMA16816(acc[1][nb], ah1, bfr[nb].z, bfr[nb].w);
            }
        }
    };

    // ---- pipeline (unrolled x2, compile-time stages) ----
    LOADB();            // chunk 0
    LOADA(0);
    STORESA(0);
    __syncthreads();
    for (int ch = 0; ch < NCH; ch += 2) {
        LOADA(ch + 1);
        COMPUTE(0);
        LOADB();        // bfr <- ch+1
        STORESA(1);
        __syncthreads();
        bool more = (ch + 2 < NCH);
        if (more) LOADA(ch + 2);
        COMPUTE(1);
        if (more) {
            LOADB();    // bfr <- ch+2
            STORESA(0);
        }
        __syncthreads();
    }

    // ---- epilogue: write accum -> g_h ----
    const int gcol = g * CO + n_base + wn;
    const int r    = lane >> 2;
    const int c    = (lane & 3) * 2;
    #pragma unroll
    for (int mi = 0; mi < 2; mi++) {
        int m = m_base + wm + mi * 16 + r;
        #pragma unroll
        for (int nt = 0; nt < 8; nt++) {
            int n = gcol + nt * 8 + c;
            float2 v0 = make_float2(acc[mi][nt][0], acc[mi][nt][1]);
            float2 v1 = make_float2(acc[mi][nt][2], acc[mi][nt][3]);
            *(float2*)&g_h[(size_t)m * WW + n]       = v0;
            *(float2*)&g_h[(size_t)(m + 8) * WW + n] = v1;
        }
    }
}

// ============================================================
// Kernel 4: per-row LayerNorm + mask + projection dot
// ============================================================
__global__ void ln_proj_kernel(const float* __restrict__ conv_b,
                               const float* __restrict__ gamma,
                               const float* __restrict__ beta,
                               const float* __restrict__ proj_w,
                               const int* __restrict__ mask) {
    int row = blockIdx.x;
    int tid = threadIdx.x;   // 256
    const float* hr = &g_h[(size_t)row * WW];

    float v[4];
    float s = 0.f, ss = 0.f;
    #pragma unroll
    for (int i = 0; i < 4; i++) {
        int w = tid + i * 256;
        float hv = hr[w] + conv_b[w];
        v[i] = hv;
        s  += hv;
        ss += hv * hv;
    }
    __shared__ float shA[8], shB[8];
    __shared__ float mu_sh, rstd_sh;
    #pragma unroll
    for (int o = 16; o > 0; o >>= 1) {
        s  += __shfl_xor_sync(0xffffffff, s,  o);
        ss += __shfl_xor_sync(0xffffffff, ss, o);
    }
    int warp = tid >> 5, lane = tid & 31;
    if (lane == 0) { shA[warp] = s; shB[warp] = ss; }
    __syncthreads();
    if (tid == 0) {
        float S = 0.f, SS = 0.f;
        #pragma unroll
        for (int i = 0; i < 8; i++) { S += shA[i]; SS += shB[i]; }
        float mu = S / (float)WW;
        float var = SS / (float)WW - mu * mu;
        mu_sh = mu;
        rstd_sh = rsqrtf(var + 1e-5f);
    }
    __syncthreads();
    float mu = mu_sh, rstd = rstd_sh;

    float dot = 0.f;
    #pragma unroll
    for (int i = 0; i < 4; i++) {
        int w = tid + i * 256;
        dot += ((v[i] - mu) * rstd * gamma[w] + beta[w]) * proj_w[w];
    }
    #pragma unroll
    for (int o = 16; o > 0; o >>= 1)
        dot += __shfl_xor_sync(0xffffffff, dot, o);
    __syncthreads();
    if (lane == 0) shA[warp] = dot;
    __syncthreads();
    if (tid == 0) {
        float D = 0.f;
        #pragma unroll
        for (int i = 0; i < 8; i++) D += shA[i];
        g_s[row] = (mask[row] != 0) ? 0.f : D;
    }
}

// ============================================================
// Kernel 5: final masked mean over L + proj_b
// ============================================================
__global__ void final_kernel(const int* __restrict__ mask,
                             const float* __restrict__ proj_b,
                             float* __restrict__ out) {
    int b = blockIdx.x;
    int tid = threadIdx.x;  // 256
    float s = 0.f;
    int cnt = 0;
    for (int l = tid; l < LL; l += 256) {
        s += g_s[b * LL + l];
        cnt += (mask[b * LL + l] != 0) ? 0 : 1;
    }
    #pragma unroll
    for (int o = 16; o > 0; o >>= 1) {
        s   += __shfl_xor_sync(0xffffffff, s, o);
        cnt += __shfl_xor_sync(0xffffffff, cnt, o);
    }
    __shared__ float shS[8];
    __shared__ int   shC[8];
    int warp = tid >> 5, lane = tid & 31;
    if (lane == 0) { shS[warp] = s; shC[warp] = cnt; }
    __syncthreads();
    if (tid == 0) {
        float S = 0.f; int C = 0;
        #pragma unroll
        for (int i = 0; i < 8; i++) { S += shS[i]; C += shC[i]; }
        float len = fmaxf((float)C, 1.0f);
        out[b] = S / len + proj_b[0];
    }
}

// ============================================================
extern "C" void kernel_launch(void* const* d_in, const int* in_sizes, int n_in,
                              void* d_out, int out_size) {
    const float* x       = (const float*)d_in[0];
    const int*   mask    = (const int*)d_in[1];
    const float* w_off   = (const float*)d_in[2];
    const float* b_off   = (const float*)d_in[3];
    const float* conv_w  = (const float*)d_in[4];
    const float* conv_b  = (const float*)d_in[5];
    const float* gamma   = (const float*)d_in[6];
    const float* beta    = (const float*)d_in[7];
    const float* proj_w  = (const float*)d_in[8];
    const float* proj_b  = (const float*)d_in[9];
    float* out = (float*)d_out;

    cudaFuncSetAttribute(conv_mma_kernel,
                         cudaFuncAttributeMaxDynamicSharedMemorySize, SMEM_CONV);

    prep_b_kernel<<<(GG*NQ*NCH*4*32 + 255) / 256, 256>>>(conv_w);
    offsets_kernel<<<BB * LL, 128>>>(x, w_off, b_off);
    dim3 cgrid(GG * 4, (BB * LL) / MT);   // (8, 256)
    conv_mma_kernel<<<cgrid, 128, SMEM_CONV>>>();
    ln_proj_kernel<<<BB * LL, 256>>>(conv_b, gamma, beta, proj_w, mask);
    final_kernel<<<BB, 256>>>(mask, proj_b, out);
}